// round 11
// baseline (speedup 1.0000x reference)
#include <cuda_runtime.h>
#include <cuda_fp16.h>
#include <math.h>
#include <stdint.h>

#define SEQ   2048
#define HID   2048
#define INSZ  1024
#define NL    4
#define NMAT  7
#define HIST_T (SEQ + 1)
#define SENT  0xFFFFFFFFu
#define NW4   ((size_t)4 * HID * HID)
#define NTOT  ((size_t)7 * HID * HID)
#define HU_TOTAL (14 * HID)          // 7 matrices * 2 K-halves * 2048 rows

// ---------------- persistent device scratch ----------------
__device__ __half   g_w16[NTOT];
__device__ float    g_hist[NL][HIST_T][HID];   // h_l(t) at [l][t+1]; [l][0]=0
__device__ float    g_xin[(size_t)SEQ * HID];
__device__ unsigned g_hslot[NMAT * HID];       // K-half merge slots
__device__ unsigned g_slot[3 * HID];           // cross-matrix merge slots
__device__ unsigned g_done[NL * 64];           // per-layer completion counters
__device__ unsigned g_cnt = 0;                 // init barrier
__device__ unsigned g_gen = 0;

// ---------------- scoped strong-op helpers (no CCTL.IVALL) ----------------
__device__ __forceinline__ void st_relaxed_f32(float* p, float v) {
    asm volatile("st.relaxed.gpu.global.f32 [%0], %1;" :: "l"(p), "f"(v));
}
__device__ __forceinline__ void st_relaxed_u32(unsigned* p, unsigned v) {
    asm volatile("st.relaxed.gpu.global.u32 [%0], %1;" :: "l"(p), "r"(v));
}
__device__ __forceinline__ unsigned ld_acquire_u32(const unsigned* p) {
    unsigned v;
    asm volatile("ld.acquire.gpu.global.u32 %0, [%1];" : "=r"(v) : "l"(p));
    return v;
}
__device__ __forceinline__ void red_release_add(unsigned* p, unsigned v) {
    asm volatile("red.release.gpu.global.add.u32 [%0], %1;" :: "l"(p), "r"(v));
}
// gate: spin until done[l] >= target
__device__ __forceinline__ void wait_done(int l, unsigned target) {
    const unsigned* p = &g_done[l * 64];
    while (ld_acquire_u32(p) < target) { }
}

// ---------------- weight conversion fp32 -> fp16 ----------------
__global__ void convert_w_kernel(const float* __restrict__ Wh,
                                 const float* __restrict__ Whh)
{
    const size_t n4  = NTOT / 4;
    const size_t nw4 = NW4 / 4;
    for (size_t i = (size_t)blockIdx.x * blockDim.x + threadIdx.x;
         i < n4; i += (size_t)gridDim.x * blockDim.x) {
        float4 v = (i < nw4) ? ((const float4*)Wh)[i]
                             : ((const float4*)Whh)[i - nw4];
        __half2* dst = (__half2*)g_w16 + 2 * i;
        dst[0] = __floats2half2_rn(v.x, v.y);
        dst[1] = __floats2half2_rn(v.z, v.w);
    }
}

__global__ void noop_kernel() {}   // pad: keeps the wave kernel in ncu's capture slot

__global__ void copy_hfinal_kernel(float* hfinal_out)
{
    int i = blockIdx.x * blockDim.x + threadIdx.x;
    if (i < NL * HID)
        hfinal_out[i] = g_hist[i >> 11][SEQ][i & (HID - 1)];
}

// ---------------- init barrier (once per launch; one IVALL is fine) -------
__device__ __forceinline__ void init_barrier(unsigned nb)
{
    __syncthreads();
    if (threadIdx.x == 0) {
        __threadfence();
        volatile unsigned* vgen = &g_gen;
        unsigned g = *vgen;
        if (atomicAdd(&g_cnt, 1u) == nb - 1u) {
            g_cnt = 0u;
            __threadfence();
            *vgen = g + 1u;
        } else {
            while (*vgen == g) { }
            __threadfence();
        }
    }
    __syncthreads();
}

// ---------------- element finish: two-level exch-sentinel + done ----------
__device__ __forceinline__ void finish_partial(int m, int l, int r, int t,
                                               float p, const float* __restrict__ Bh)
{
    unsigned* hs = &g_hslot[m * HID + r];
    unsigned old = atomicExch(hs, __float_as_uint(p));
    if (old == SENT) return;                  // first K-half arriver
    float full = p + __uint_as_float(old);
    st_relaxed_u32(hs, SENT);
    if (m == 0) {
        float v = full + Bh[r] + __ldcg(g_xin + (size_t)t * HID + r);
        st_relaxed_f32(&g_hist[0][t + 1][r], tanhf(v));
        red_release_add(&g_done[0], 1u);
    } else {
        float q = full + ((m < 4) ? Bh[m * HID + r] : 0.f);
        unsigned* cs = &g_slot[(l - 1) * HID + r];
        unsigned old2 = atomicExch(cs, __float_as_uint(q));
        if (old2 == SENT) return;             // first matrix arriver
        float tot = q + __uint_as_float(old2);
        st_relaxed_u32(cs, SENT);
        st_relaxed_f32(&g_hist[l][t + 1][r], tanhf(tot));
        red_release_add(&g_done[l * 64], 1u);
    }
}

// ---------------- generic single half-unit (boundary warps) ---------------
__device__ __forceinline__ void run_unit(int f, int t, int lane,
                                         const float* __restrict__ Bh)
{
    const int sg = f >> 11, mm = sg >> 1, hf = sg & 1, r = f & 2047;
    const int ll  = (mm < 4) ? mm : mm - 3;
    const int src = (mm < 4) ? mm : mm - 4;
    // gates
    if (mm < 4) {
        wait_done(mm, 2048u * (unsigned)t);
    } else {
        wait_done(src, 2048u * (unsigned)(t + 1));
        wait_done(ll,  2048u * (unsigned)t);
    }
    const int hidx = (mm < 4) ? t : t + 1;
    const uint4*  w4 = (const uint4*)(g_w16 + ((size_t)mm * HID + r) * HID) + hf * 128;
    const float4* h4 = (const float4*)(&g_hist[src][hidx][0]) + hf * 256;
    float a0 = 0.f, a1 = 0.f;
    #pragma unroll
    for (int i = 0; i < 4; ++i) {
        const int idx = lane + 32 * i;
        uint4 wv = (mm < 3) ? w4[idx] : __ldcg(w4 + idx);
        float4 h0 = h4[2 * idx];
        float4 h1 = h4[2 * idx + 1];
        float2 c;
        c = __half22float2(*(__half2*)&wv.x); a0 = fmaf(c.x, h0.x, a0); a1 = fmaf(c.y, h0.y, a1);
        c = __half22float2(*(__half2*)&wv.y); a0 = fmaf(c.x, h0.z, a0); a1 = fmaf(c.y, h0.w, a1);
        c = __half22float2(*(__half2*)&wv.z); a0 = fmaf(c.x, h1.x, a0); a1 = fmaf(c.y, h1.y, a1);
        c = __half22float2(*(__half2*)&wv.w); a0 = fmaf(c.x, h1.z, a0); a1 = fmaf(c.y, h1.w, a1);
    }
    float acc = a0 + a1;
    #pragma unroll
    for (int s = 16; s; s >>= 1) acc += __shfl_xor_sync(0xffffffffu, acc, s);
    if (lane == 0) finish_partial(mm, ll, r, t, acc, Bh);
}

// ---------------- dataflow RNN kernel (no grid barrier) --------------------
__global__ __launch_bounds__(1024, 1) void rnn_wave_kernel(
    const float* __restrict__ Bh)
{
    const unsigned nb  = gridDim.x;
    const int tid      = threadIdx.x;
    const int gtid     = blockIdx.x * 1024 + tid;
    const int nthreads = (int)nb * 1024;

    // per-launch init (graph replays reuse device globals)
    for (int i = gtid; i < NL * HID; i += nthreads)
        g_hist[i >> 11][0][i & (HID - 1)] = 0.f;     // h(t=-1) = 0
    for (int i = gtid; i < NMAT * HID; i += nthreads) g_hslot[i] = SENT;
    for (int i = gtid; i < 3 * HID; i += nthreads)    g_slot[i]  = SENT;
    for (int i = gtid; i < NL * 64; i += nthreads)    g_done[i]  = 0u;
    init_barrier(nb);

    const int lane = tid & 31;
    const int gw   = (blockIdx.x << 5) + (tid >> 5);

    // ---- static warp assignment ----
    const int flat0 = 6 * gw;
    if (flat0 >= HU_TOTAL) return;                   // idle tail warps
    const bool fast = (flat0 + 5 < HU_TOTAL) && ((flat0 & 2047) <= 2042);

    if (fast) {
        const int seg  = flat0 >> 11;
        const int m    = seg >> 1;
        const int half = seg & 1;
        const int r0   = flat0 & 2047;
        const int l    = (m < 4) ? m : m - 3;
        const int src  = (m < 4) ? m : m - 4;
        const uint4* wbase = (const uint4*)(g_w16 + (size_t)m * HID * HID)
                             + (size_t)r0 * 256 + half * 128;   // row j at +j*256

        for (int t = 0; t < SEQ; ++t) {
            // gates (same for all 6 units of this warp)
            if (m < 4) {
                wait_done(m, 2048u * (unsigned)t);
            } else {
                wait_done(src, 2048u * (unsigned)(t + 1));
                wait_done(l,   2048u * (unsigned)t);
            }
            const int hidx = (m < 4) ? t : t + 1;
            const float4* h4 = (const float4*)(&g_hist[src][hidx][0]) + half * 256;

            float acc[6];
            #pragma unroll
            for (int j = 0; j < 6; ++j) acc[j] = 0.f;

            #pragma unroll
            for (int i = 0; i < 4; ++i) {
                const int idx = lane + 32 * i;
                const float4 h0 = h4[2 * idx];
                const float4 h1 = h4[2 * idx + 1];
                uint4 wv[6];
                if (m < 3) {
                    #pragma unroll
                    for (int j = 0; j < 6; ++j) wv[j] = wbase[j * 256 + idx];
                } else {
                    #pragma unroll
                    for (int j = 0; j < 6; ++j) wv[j] = __ldcg(wbase + j * 256 + idx);
                }
                #pragma unroll
                for (int j = 0; j < 6; ++j) {
                    float2 c;
                    c = __half22float2(*(__half2*)&wv[j].x);
                    acc[j] = fmaf(c.x, h0.x, acc[j]); acc[j] = fmaf(c.y, h0.y, acc[j]);
                    c = __half22float2(*(__half2*)&wv[j].y);
                    acc[j] = fmaf(c.x, h0.z, acc[j]); acc[j] = fmaf(c.y, h0.w, acc[j]);
                    c = __half22float2(*(__half2*)&wv[j].z);
                    acc[j] = fmaf(c.x, h1.x, acc[j]); acc[j] = fmaf(c.y, h1.y, acc[j]);
                    c = __half22float2(*(__half2*)&wv[j].w);
                    acc[j] = fmaf(c.x, h1.z, acc[j]); acc[j] = fmaf(c.y, h1.w, acc[j]);
                }
            }

            // interleaved reductions (6 independent chains)
            #pragma unroll
            for (int s = 16; s; s >>= 1) {
                #pragma unroll
                for (int j = 0; j < 6; ++j)
                    acc[j] += __shfl_xor_sync(0xffffffffu, acc[j], s);
            }

            // batched finish
            if (lane == 0) {
                unsigned old1[6];
                #pragma unroll
                for (int j = 0; j < 6; ++j)
                    old1[j] = atomicExch(&g_hslot[m * HID + r0 + j],
                                         __float_as_uint(acc[j]));
                #pragma unroll
                for (int j = 0; j < 6; ++j) {
                    if (old1[j] == SENT) continue;
                    const int r = r0 + j;
                    float full = acc[j] + __uint_as_float(old1[j]);
                    st_relaxed_u32(&g_hslot[m * HID + r], SENT);
                    if (m == 0) {
                        float v = full + Bh[r] + __ldcg(g_xin + (size_t)t * HID + r);
                        st_relaxed_f32(&g_hist[0][t + 1][r], tanhf(v));
                        red_release_add(&g_done[0], 1u);
                    } else {
                        float q = full + ((m < 4) ? Bh[m * HID + r] : 0.f);
                        unsigned old2 = atomicExch(&g_slot[(l - 1) * HID + r],
                                                   __float_as_uint(q));
                        if (old2 != SENT) {
                            float tot = q + __uint_as_float(old2);
                            st_relaxed_u32(&g_slot[(l - 1) * HID + r], SENT);
                            st_relaxed_f32(&g_hist[l][t + 1][r], tanhf(tot));
                            red_release_add(&g_done[l * 64], 1u);
                        }
                    }
                }
            }
        }
    } else {
        // boundary warps: per-unit gating
        for (int t = 0; t < SEQ; ++t) {
            #pragma unroll
            for (int j = 0; j < 6; ++j) {
                const int f = flat0 + j;
                if (f < HU_TOTAL)
                    run_unit(f, t, lane, Bh);
            }
        }
    }
}

// ---------------- generic C[M,N] = A[M,K] * B[N,K]^T (+bias) ----------------
__global__ __launch_bounds__(256) void gemm_abt_kernel(
    const float* __restrict__ A,
    const float* __restrict__ B,
    float*       __restrict__ C,
    const float* __restrict__ bias,
    int M, int N, int K)
{
    __shared__ float As[16][68];
    __shared__ float Bs[16][68];

    const int tn  = blockIdx.x * 64;
    const int tm  = blockIdx.y * 64;
    const int tid = threadIdx.x;
    const int tx  = tid & 15;
    const int ty  = tid >> 4;
    const int lr  = tid >> 2;
    const int lq  = tid & 3;

    float acc[4][4];
    #pragma unroll
    for (int i = 0; i < 4; ++i)
        #pragma unroll
        for (int j = 0; j < 4; ++j) acc[i][j] = 0.f;

    for (int k0 = 0; k0 < K; k0 += 16) {
        float4 a4 = *(const float4*)(A + (size_t)(tm + lr) * K + k0 + lq * 4);
        float4 b4 = *(const float4*)(B + (size_t)(tn + lr) * K + k0 + lq * 4);
        As[lq * 4 + 0][lr] = a4.x; As[lq * 4 + 1][lr] = a4.y;
        As[lq * 4 + 2][lr] = a4.z; As[lq * 4 + 3][lr] = a4.w;
        Bs[lq * 4 + 0][lr] = b4.x; Bs[lq * 4 + 1][lr] = b4.y;
        Bs[lq * 4 + 2][lr] = b4.z; Bs[lq * 4 + 3][lr] = b4.w;
        __syncthreads();
        #pragma unroll
        for (int kk = 0; kk < 16; ++kk) {
            float a0 = As[kk][ty * 4 + 0], a1 = As[kk][ty * 4 + 1];
            float a2 = As[kk][ty * 4 + 2], a3 = As[kk][ty * 4 + 3];
            float b0 = Bs[kk][tx * 4 + 0], b1 = Bs[kk][tx * 4 + 1];
            float b2 = Bs[kk][tx * 4 + 2], b3 = Bs[kk][tx * 4 + 3];
            acc[0][0] = fmaf(a0, b0, acc[0][0]); acc[0][1] = fmaf(a0, b1, acc[0][1]);
            acc[0][2] = fmaf(a0, b2, acc[0][2]); acc[0][3] = fmaf(a0, b3, acc[0][3]);
            acc[1][0] = fmaf(a1, b0, acc[1][0]); acc[1][1] = fmaf(a1, b1, acc[1][1]);
            acc[1][2] = fmaf(a1, b2, acc[1][2]); acc[1][3] = fmaf(a1, b3, acc[1][3]);
            acc[2][0] = fmaf(a2, b0, acc[2][0]); acc[2][1] = fmaf(a2, b1, acc[2][1]);
            acc[2][2] = fmaf(a2, b2, acc[2][2]); acc[2][3] = fmaf(a2, b3, acc[2][3]);
            acc[3][0] = fmaf(a3, b0, acc[3][0]); acc[3][1] = fmaf(a3, b1, acc[3][1]);
            acc[3][2] = fmaf(a3, b2, acc[3][2]); acc[3][3] = fmaf(a3, b3, acc[3][3]);
        }
        __syncthreads();
    }

    #pragma unroll
    for (int i = 0; i < 4; ++i) {
        const int row = tm + ty * 4 + i;
        #pragma unroll
        for (int j = 0; j < 4; ++j) {
            const int col = tn + tx * 4 + j;
            float v = acc[i][j];
            if (bias) v += bias[col];
            C[(size_t)row * N + col] = v;
        }
    }
}

// ---------------- launch ----------------
extern "C" void kernel_launch(void* const* d_in, const int* in_sizes, int n_in,
                              void* d_out, int out_size)
{
    const float* x   = (const float*)d_in[0];
    const float* Wh  = (const float*)d_in[1];
    const float* Whh = (const float*)d_in[2];
    const float* Wx  = (const float*)d_in[3];
    const float* Wy  = (const float*)d_in[4];
    const float* Bh  = (const float*)d_in[5];
    const float* By  = (const float*)d_in[6];
    float* out = (float*)d_out;

    (void)in_sizes; (void)n_in;

    void* p_xin  = nullptr;
    void* p_hist = nullptr;
    cudaGetSymbolAddress(&p_xin,  g_xin);
    cudaGetSymbolAddress(&p_hist, g_hist);

    int nsm = 0;
    cudaDeviceGetAttribute(&nsm, cudaDevAttrMultiProcessorCount, 0);
    if (nsm <= 0) nsm = 148;

    cudaFuncSetAttribute(rnn_wave_kernel,
                         cudaFuncAttributePreferredSharedMemoryCarveout, 0);

    // 1) fp32 -> fp16 weight conversion
    convert_w_kernel<<<nsm * 8, 256>>>(Wh, Whh);

    // 2) xin = x @ Wx^T
    {
        dim3 grid(HID / 64, SEQ / 64);
        gemm_abt_kernel<<<grid, 256>>>(x, Wx, (float*)p_xin, nullptr,
                                       SEQ, HID, INSZ);
    }

    // 3) pad so the wave kernel stays in ncu's capture slot
    noop_kernel<<<1, 32>>>();

    // 4) dataflow recurrence (persistent kernel, grid = #SMs, no grid barrier)
    rnn_wave_kernel<<<nsm, 1024>>>(Bh);

    // 5) ys = h3_all @ Wy^T + By   (A = hist[3][1..2048])
    {
        const float* h3 = (const float*)p_hist + ((size_t)3 * HIST_T + 1) * HID;
        dim3 grid(INSZ / 64, SEQ / 64);
        gemm_abt_kernel<<<grid, 256>>>(h3, Wy, out, By, SEQ, INSZ, HID);
    }

    // 6) h_final = hist[:, 2048, :]
    if (out_size >= SEQ * INSZ + NL * HID)
        copy_hfinal_kernel<<<(NL * HID + 255) / 256, 256>>>(out + (size_t)SEQ * INSZ);
}

// round 12
// speedup vs baseline: 3.8684x; 3.8684x over previous
#include <cuda_runtime.h>
#include <cuda_fp16.h>
#include <math.h>
#include <stdint.h>

#define SEQ   2048
#define HID   2048
#define INSZ  1024
#define NL    4
#define NMAT  7
#define SENT  0xFFFFFFFFu
#define NW4   ((size_t)4 * HID * HID)
#define NTOT  ((size_t)7 * HID * HID)
#define NCTR  32
#define HU_TOTAL (14 * HID)          // 7 matrices * 2 K-halves * 2048 rows

// ---------------- persistent device scratch ----------------
__device__ __half   g_w16[NTOT];
__device__ float    g_h[NL][2][HID];
__device__ float    g_xin[(size_t)SEQ * HID];
__device__ float    g_h3[(size_t)SEQ * HID];
__device__ unsigned g_hslot[NMAT * HID];  // K-half merge slots
__device__ unsigned g_slot[3 * HID];      // cross-matrix merge slots
__device__ unsigned g_ctr[NCTR * 64];
__device__ unsigned g_cnt = 0;
__device__ unsigned g_gen = 0;

// ---------------- scoped strong-op helpers (no CCTL.IVALL) ----------------
__device__ __forceinline__ void st_relaxed_f32(float* p, float v) {
    asm volatile("st.relaxed.gpu.global.f32 [%0], %1;" :: "l"(p), "f"(v));
}
__device__ __forceinline__ void st_relaxed_u32(unsigned* p, unsigned v) {
    asm volatile("st.relaxed.gpu.global.u32 [%0], %1;" :: "l"(p), "r"(v));
}
__device__ __forceinline__ unsigned ld_acquire_u32(const unsigned* p) {
    unsigned v;
    asm volatile("ld.acquire.gpu.global.u32 %0, [%1];" : "=r"(v) : "l"(p));
    return v;
}
__device__ __forceinline__ void red_release_add(unsigned* p, unsigned v) {
    asm volatile("red.release.gpu.global.add.u32 [%0], %1;" :: "l"(p), "r"(v));
}

// ---------------- weight conversion fp32 -> fp16 ----------------
__global__ void convert_w_kernel(const float* __restrict__ Wh,
                                 const float* __restrict__ Whh)
{
    const size_t n4  = NTOT / 4;
    const size_t nw4 = NW4 / 4;
    for (size_t i = (size_t)blockIdx.x * blockDim.x + threadIdx.x;
         i < n4; i += (size_t)gridDim.x * blockDim.x) {
        float4 v = (i < nw4) ? ((const float4*)Wh)[i]
                             : ((const float4*)Whh)[i - nw4];
        __half2* dst = (__half2*)g_w16 + 2 * i;
        dst[0] = __floats2half2_rn(v.x, v.y);
        dst[1] = __floats2half2_rn(v.z, v.w);
    }
}

__global__ void noop_kernel() {}   // pad: keeps the wave kernel in ncu's capture slot

// ---------------- legacy fenced barrier (init only) ----------------
__device__ __forceinline__ void init_barrier(unsigned nb)
{
    __syncthreads();
    if (threadIdx.x == 0) {
        __threadfence();
        volatile unsigned* vgen = &g_gen;
        unsigned g = *vgen;
        if (atomicAdd(&g_cnt, 1u) == nb - 1u) {
            g_cnt = 0u;
            __threadfence();
            *vgen = g + 1u;
        } else {
            while (*vgen == g) { }
            __threadfence();
        }
    }
    __syncthreads();
}

// ---------------- IVALL-free wave barrier (release/acquire, proven) -------
__device__ __forceinline__ void wave_barrier(unsigned nb, unsigned epoch)
{
    __syncthreads();
    if (threadIdx.x == 0)
        red_release_add(&g_ctr[(blockIdx.x & (NCTR - 1)) * 64], 1u);
    if (threadIdx.x < NCTR) {
        const unsigned i = threadIdx.x;
        const unsigned per = (nb - i + NCTR - 1) / NCTR;   // #blocks, bid%NCTR==i
        const unsigned target = per * epoch;
        while (ld_acquire_u32(&g_ctr[i * 64]) < target) { }
    }
    __syncthreads();
}

// ---------------- batched row-group GEMV + finish --------------------------
// Processes nr (1..7) consecutive rows of segment (m, half), h from staged
// smem slot, xin from staged smem (m==0). All lanes participate; atomics on
// lane 0 are batched (independent addresses, pipelined in the LTS).
__device__ __forceinline__ void batch_rows(
    int m, int half, int r0, int nr, int w, int lane,
    const float* __restrict__ sm_slot,   // staged 1024 floats (hsrc, half)
    const float* __restrict__ sm_xin,    // staged xin row (t = w), m==0 only
    const float* __restrict__ Bh)
{
    const int l = (m < 4) ? m : m - 3;
    const int t = w - l;
    if ((unsigned)t >= (unsigned)SEQ) return;

    const uint4* wb = (const uint4*)(g_w16 + (size_t)m * HID * HID)
                      + (size_t)r0 * 256 + half * 128;     // row j at +j*256
    const float4* h4 = (const float4*)sm_slot;

    float acc[7];
    #pragma unroll
    for (int j = 0; j < 7; ++j) acc[j] = 0.f;

    #pragma unroll
    for (int i = 0; i < 4; ++i) {
        const int idx = lane + 32 * i;
        const float4 h0 = h4[2 * idx];
        const float4 h1 = h4[2 * idx + 1];
        #pragma unroll
        for (int j = 0; j < 7; ++j) {
            if (j < nr) {
                uint4 wv = (m < 3) ? wb[j * 256 + idx]
                                   : __ldcg(wb + j * 256 + idx);
                float2 c;
                c = __half22float2(*(__half2*)&wv.x);
                acc[j] = fmaf(c.x, h0.x, acc[j]); acc[j] = fmaf(c.y, h0.y, acc[j]);
                c = __half22float2(*(__half2*)&wv.y);
                acc[j] = fmaf(c.x, h0.z, acc[j]); acc[j] = fmaf(c.y, h0.w, acc[j]);
                c = __half22float2(*(__half2*)&wv.z);
                acc[j] = fmaf(c.x, h1.x, acc[j]); acc[j] = fmaf(c.y, h1.y, acc[j]);
                c = __half22float2(*(__half2*)&wv.w);
                acc[j] = fmaf(c.x, h1.z, acc[j]); acc[j] = fmaf(c.y, h1.w, acc[j]);
            }
        }
    }

    // interleaved reductions (nr independent chains; predicate warp-uniform)
    #pragma unroll
    for (int s = 16; s; s >>= 1) {
        #pragma unroll
        for (int j = 0; j < 7; ++j)
            if (j < nr)
                acc[j] += __shfl_xor_sync(0xffffffffu, acc[j], s);
    }

    if (lane == 0) {
        unsigned old1[7];
        #pragma unroll
        for (int j = 0; j < 7; ++j)
            if (j < nr)
                old1[j] = atomicExch(&g_hslot[m * HID + r0 + j],
                                     __float_as_uint(acc[j]));
        #pragma unroll
        for (int j = 0; j < 7; ++j) {
            if (j >= nr || old1[j] == SENT) continue;
            const int r = r0 + j;
            float full = acc[j] + __uint_as_float(old1[j]);
            st_relaxed_u32(&g_hslot[m * HID + r], SENT);
            if (m == 0) {
                float v = full + Bh[r] + sm_xin[r];
                st_relaxed_f32(&g_h[0][t & 1][r], tanhf(v));
            } else {
                float q = full + ((m < 4) ? Bh[l * HID + r] : 0.f);
                unsigned old2 = atomicExch(&g_slot[(l - 1) * HID + r],
                                           __float_as_uint(q));
                if (old2 != SENT) {
                    float tot = q + __uint_as_float(old2);
                    st_relaxed_u32(&g_slot[(l - 1) * HID + r], SENT);
                    float hv = tanhf(tot);
                    st_relaxed_f32(&g_h[l][t & 1][r], hv);
                    if (l == 3) st_relaxed_f32(&g_h3[(size_t)t * HID + r], hv);
                }
            }
        }
    }
}

// assignment: warp gw gets nr units starting at f0 (covers HU_TOTAL exactly)
__device__ __forceinline__ void warp_range(int gw, int nwarp, int& f0, int& nr)
{
    const int q   = HU_TOTAL / nwarp;
    const int rem = HU_TOTAL % nwarp;
    if (gw < rem) { nr = q + 1; f0 = (q + 1) * gw; }
    else          { nr = q;     f0 = rem * (q + 1) + q * (gw - rem); }
}

// ---------------- wavefront RNN kernel ----------------
__global__ __launch_bounds__(1024, 1) void rnn_wave_kernel(
    const float* __restrict__ Bh,
    float*                    hfinal_out)
{
    __shared__ float sm_hh[2][1024];   // block's two staged h segment-halves
    __shared__ float sm_xin[HID];      // staged xin row (t = w)

    const unsigned nb  = gridDim.x;
    const int tid      = threadIdx.x;
    const int gtid     = blockIdx.x * 1024 + tid;
    const int nthreads = (int)nb * 1024;

    for (int i = gtid; i < NL * 2 * HID; i += nthreads) ((float*)g_h)[i] = 0.f;
    for (int i = gtid; i < NMAT * HID; i += nthreads)   g_hslot[i] = SENT;
    for (int i = gtid; i < 3 * HID; i += nthreads)      g_slot[i]  = SENT;
    for (int i = gtid; i < NCTR * 64; i += nthreads)    g_ctr[i]   = 0u;
    init_barrier(nb);

    const int lane  = tid & 31;
    const int gw    = (blockIdx.x << 5) + (tid >> 5);
    const int nwarp = (int)nb * 32;

    // ---- wave-invariant warp assignment (uniform batch, no serial extras) --
    int f0, nr;
    warp_range(gw, nwarp, f0, nr);
    const int n1 = min(nr, HID - (f0 & (HID - 1)));   // rows before segment edge
    const int segA = f0 >> 11;
    const int segB = (n1 < nr) ? segA + 1 : segA;
    const int mA = segA >> 1, halfA = segA & 1, rA = f0 & (HID - 1);
    const int mB = segB >> 1, halfB = segB & 1;

    // ---- block's two staged segments ----
    int bf_lo, bn_lo, bf_hi, bn_hi;
    warp_range(blockIdx.x << 5, nwarp, bf_lo, bn_lo);
    warp_range((blockIdx.x << 5) + 31, nwarp, bf_hi, bn_hi);
    const int seg0 = bf_lo >> 11;
    const int seg1 = (bf_hi + bn_hi - 1) >> 11;
    const int slotA = (segA == seg0) ? 0 : 1;
    const int slotB = (segB == seg0) ? 0 : 1;

    // staging params (wave-invariant)
    const int sslot  = tid >> 8;                // 0/1 for tid<512
    const int sidx   = tid & 255;
    const int ssg    = sslot ? seg1 : seg0;
    const int ssm    = ssg >> 1;
    const int sshalf = ssg & 1;
    const int sshsrc = (ssm < 4) ? ssm : ssm - 4;

    unsigned epoch = 0;

    for (int w = 0; w < SEQ + NL - 1; ++w) {
        // stage: 2 h segment-halves (tid<512) + xin row (tid>=512)
        if (tid < 512) {
            const int spar = (w + sshsrc + 1) & 1;
            ((float4*)sm_hh[sslot])[sidx] =
                __ldcg((const float4*)(g_h[sshsrc][spar]) + sshalf * 256 + sidx);
        } else if (w < SEQ) {
            ((float4*)sm_xin)[tid - 512] =
                __ldcg((const float4*)(g_xin + (size_t)w * HID) + (tid - 512));
        }
        __syncthreads();

        batch_rows(mA, halfA, rA, n1, w, lane, sm_hh[slotA], sm_xin, Bh);
        if (n1 < nr)
            batch_rows(mB, halfB, 0, nr - n1, w, lane, sm_hh[slotB], sm_xin, Bh);

        ++epoch;
        wave_barrier(nb, epoch);
    }

    if (hfinal_out) {
        for (int i = gtid; i < NL * HID; i += nthreads)
            hfinal_out[i] = __ldcg(&g_h[i >> 11][1][i & (HID - 1)]);
    }
}

// ---------------- generic C[M,N] = A[M,K] * B[N,K]^T (+bias) ----------------
__global__ __launch_bounds__(256) void gemm_abt_kernel(
    const float* __restrict__ A,
    const float* __restrict__ B,
    float*       __restrict__ C,
    const float* __restrict__ bias,
    int M, int N, int K)
{
    __shared__ float As[16][68];
    __shared__ float Bs[16][68];

    const int tn  = blockIdx.x * 64;
    const int tm  = blockIdx.y * 64;
    const int tid = threadIdx.x;
    const int tx  = tid & 15;
    const int ty  = tid >> 4;
    const int lr  = tid >> 2;
    const int lq  = tid & 3;

    float acc[4][4];
    #pragma unroll
    for (int i = 0; i < 4; ++i)
        #pragma unroll
        for (int j = 0; j < 4; ++j) acc[i][j] = 0.f;

    for (int k0 = 0; k0 < K; k0 += 16) {
        float4 a4 = *(const float4*)(A + (size_t)(tm + lr) * K + k0 + lq * 4);
        float4 b4 = *(const float4*)(B + (size_t)(tn + lr) * K + k0 + lq * 4);
        As[lq * 4 + 0][lr] = a4.x; As[lq * 4 + 1][lr] = a4.y;
        As[lq * 4 + 2][lr] = a4.z; As[lq * 4 + 3][lr] = a4.w;
        Bs[lq * 4 + 0][lr] = b4.x; Bs[lq * 4 + 1][lr] = b4.y;
        Bs[lq * 4 + 2][lr] = b4.z; Bs[lq * 4 + 3][lr] = b4.w;
        __syncthreads();
        #pragma unroll
        for (int kk = 0; kk < 16; ++kk) {
            float a0 = As[kk][ty * 4 + 0], a1 = As[kk][ty * 4 + 1];
            float a2 = As[kk][ty * 4 + 2], a3 = As[kk][ty * 4 + 3];
            float b0 = Bs[kk][tx * 4 + 0], b1 = Bs[kk][tx * 4 + 1];
            float b2 = Bs[kk][tx * 4 + 2], b3 = Bs[kk][tx * 4 + 3];
            acc[0][0] = fmaf(a0, b0, acc[0][0]); acc[0][1] = fmaf(a0, b1, acc[0][1]);
            acc[0][2] = fmaf(a0, b2, acc[0][2]); acc[0][3] = fmaf(a0, b3, acc[0][3]);
            acc[1][0] = fmaf(a1, b0, acc[1][0]); acc[1][1] = fmaf(a1, b1, acc[1][1]);
            acc[1][2] = fmaf(a1, b2, acc[1][2]); acc[1][3] = fmaf(a1, b3, acc[1][3]);
            acc[2][0] = fmaf(a2, b0, acc[2][0]); acc[2][1] = fmaf(a2, b1, acc[2][1]);
            acc[2][2] = fmaf(a2, b2, acc[2][2]); acc[2][3] = fmaf(a2, b3, acc[2][3]);
            acc[3][0] = fmaf(a3, b0, acc[3][0]); acc[3][1] = fmaf(a3, b1, acc[3][1]);
            acc[3][2] = fmaf(a3, b2, acc[3][2]); acc[3][3] = fmaf(a3, b3, acc[3][3]);
        }
        __syncthreads();
    }

    #pragma unroll
    for (int i = 0; i < 4; ++i) {
        const int row = tm + ty * 4 + i;
        #pragma unroll
        for (int j = 0; j < 4; ++j) {
            const int col = tn + tx * 4 + j;
            float v = acc[i][j];
            if (bias) v += bias[col];
            C[(size_t)row * N + col] = v;
        }
    }
}

// ---------------- launch ----------------
extern "C" void kernel_launch(void* const* d_in, const int* in_sizes, int n_in,
                              void* d_out, int out_size)
{
    const float* x   = (const float*)d_in[0];
    const float* Wh  = (const float*)d_in[1];
    const float* Whh = (const float*)d_in[2];
    const float* Wx  = (const float*)d_in[3];
    const float* Wy  = (const float*)d_in[4];
    const float* Bh  = (const float*)d_in[5];
    const float* By  = (const float*)d_in[6];
    float* out = (float*)d_out;

    (void)in_sizes; (void)n_in;

    void* p_xin = nullptr;
    void* p_h3  = nullptr;
    cudaGetSymbolAddress(&p_xin, g_xin);
    cudaGetSymbolAddress(&p_h3,  g_h3);

    int nsm = 0;
    cudaDeviceGetAttribute(&nsm, cudaDevAttrMultiProcessorCount, 0);
    if (nsm <= 0) nsm = 148;

    cudaFuncSetAttribute(rnn_wave_kernel,
                         cudaFuncAttributePreferredSharedMemoryCarveout, 0);

    // 1) fp32 -> fp16 weight conversion
    convert_w_kernel<<<nsm * 8, 256>>>(Wh, Whh);

    // 2) xin = x @ Wx^T
    {
        dim3 grid(HID / 64, SEQ / 64);
        gemm_abt_kernel<<<grid, 256>>>(x, Wx, (float*)p_xin, nullptr,
                                       SEQ, HID, INSZ);
    }

    // 3) pad so the wave kernel stays in ncu's capture slot
    noop_kernel<<<1, 32>>>();

    // 4) wavefront recurrence (persistent kernel, grid = #SMs)
    {
        float* hfinal = nullptr;
        if (out_size >= SEQ * INSZ + NL * HID)
            hfinal = out + (size_t)SEQ * INSZ;
        rnn_wave_kernel<<<nsm, 1024>>>(Bh, hfinal);
    }

    // 5) ys = h3_all @ Wy^T + By
    {
        dim3 grid(INSZ / 64, SEQ / 64);
        gemm_abt_kernel<<<grid, 256>>>((const float*)p_h3, Wy, out, By,
                                       SEQ, INSZ, HID);
    }
}

// round 13
// speedup vs baseline: 4.7418x; 1.2258x over previous
#include <cuda_runtime.h>
#include <cuda_fp16.h>
#include <math.h>
#include <stdint.h>

#define SEQ   2048
#define HID   2048
#define INSZ  1024
#define NL    4
#define NMAT  7
#define SENT  0xFFFFFFFFu
#define NW4   ((size_t)4 * HID * HID)
#define NTOT  ((size_t)7 * HID * HID)
#define NCTR  32
#define HU_TOTAL (14 * HID)          // 7 matrices * 2 K-halves * 2048 rows

// ---------------- persistent device scratch ----------------
__device__ __half   g_w16[NTOT];
__device__ float    g_h[NL][2][HID];
__device__ float    g_xin[(size_t)SEQ * HID];
__device__ float    g_h3[(size_t)SEQ * HID];
__device__ unsigned g_hslot[NMAT * HID];  // K-half merge slots
__device__ unsigned g_slot[3 * HID];      // cross-matrix merge slots
__device__ unsigned g_ctr[NCTR * 64];
__device__ unsigned g_cnt = 0;
__device__ unsigned g_gen = 0;

// ---------------- scoped strong-op helpers (no CCTL.IVALL) ----------------
__device__ __forceinline__ void st_relaxed_f32(float* p, float v) {
    asm volatile("st.relaxed.gpu.global.f32 [%0], %1;" :: "l"(p), "f"(v));
}
__device__ __forceinline__ void st_relaxed_u32(unsigned* p, unsigned v) {
    asm volatile("st.relaxed.gpu.global.u32 [%0], %1;" :: "l"(p), "r"(v));
}
__device__ __forceinline__ unsigned ld_acquire_u32(const unsigned* p) {
    unsigned v;
    asm volatile("ld.acquire.gpu.global.u32 %0, [%1];" : "=r"(v) : "l"(p));
    return v;
}
__device__ __forceinline__ void red_release_add(unsigned* p, unsigned v) {
    asm volatile("red.release.gpu.global.add.u32 [%0], %1;" :: "l"(p), "r"(v));
}

// ---------------- weight conversion fp32 -> fp16 ----------------
__global__ void convert_w_kernel(const float* __restrict__ Wh,
                                 const float* __restrict__ Whh)
{
    const size_t n4  = NTOT / 4;
    const size_t nw4 = NW4 / 4;
    for (size_t i = (size_t)blockIdx.x * blockDim.x + threadIdx.x;
         i < n4; i += (size_t)gridDim.x * blockDim.x) {
        float4 v = (i < nw4) ? ((const float4*)Wh)[i]
                             : ((const float4*)Whh)[i - nw4];
        __half2* dst = (__half2*)g_w16 + 2 * i;
        dst[0] = __floats2half2_rn(v.x, v.y);
        dst[1] = __floats2half2_rn(v.z, v.w);
    }
}

__global__ void noop_kernel() {}   // pad: keeps the wave kernel in ncu's capture slot

// ---------------- legacy fenced barrier (init only) ----------------
__device__ __forceinline__ void init_barrier(unsigned nb)
{
    __syncthreads();
    if (threadIdx.x == 0) {
        __threadfence();
        volatile unsigned* vgen = &g_gen;
        unsigned g = *vgen;
        if (atomicAdd(&g_cnt, 1u) == nb - 1u) {
            g_cnt = 0u;
            __threadfence();
            *vgen = g + 1u;
        } else {
            while (*vgen == g) { }
            __threadfence();
        }
    }
    __syncthreads();
}

// ---------------- IVALL-free wave barrier (release/acquire, proven) -------
__device__ __forceinline__ void wave_barrier(unsigned nb, unsigned epoch)
{
    __syncthreads();
    if (threadIdx.x == 0)
        red_release_add(&g_ctr[(blockIdx.x & (NCTR - 1)) * 64], 1u);
    if (threadIdx.x < NCTR) {
        const unsigned i = threadIdx.x;
        const unsigned per = (nb - i + NCTR - 1) / NCTR;   // #blocks, bid%NCTR==i
        const unsigned target = per * epoch;
        while (ld_acquire_u32(&g_ctr[i * 64]) < target) { }
    }
    __syncthreads();
}

// ---------------- row-finish protocol (two-level exch; boundary path) ------
__device__ __forceinline__ void finish_row_partial(int m, int r, int t, int l,
                                                   float p,
                                                   const float* __restrict__ sm_xin,
                                                   const float* __restrict__ Bh)
{
    unsigned* hs = &g_hslot[m * HID + r];
    unsigned old = atomicExch(hs, __float_as_uint(p));
    if (old == SENT) return;
    float full = p + __uint_as_float(old);
    st_relaxed_u32(hs, SENT);
    if (m == 0) {
        float v = full + Bh[r] + sm_xin[r];
        st_relaxed_f32(&g_h[0][t & 1][r], tanhf(v));
    } else {
        float q = full + ((m < 4) ? Bh[m * HID + r] : 0.f);
        unsigned* cs = &g_slot[(l - 1) * HID + r];
        unsigned old2 = atomicExch(cs, __float_as_uint(q));
        if (old2 == SENT) return;
        float tot = q + __uint_as_float(old2);
        st_relaxed_u32(cs, SENT);
        float hv = tanhf(tot);
        st_relaxed_f32(&g_h[l][t & 1][r], hv);
        if (l == 3) st_relaxed_f32(&g_h3[(size_t)t * HID + r], hv);
    }
}

// ---------------- single half-unit, h from block's staged slots -----------
__device__ __forceinline__ void process_hu_slim(int f, int seg0,
                                                const float (*sm_hh)[1024],
                                                const float* __restrict__ sm_xin,
                                                int w, int lane,
                                                const float* __restrict__ Bh)
{
    const int sg = f >> 11, mm = sg >> 1, hf = sg & 1, r = f & 2047;
    const int ll = (mm < 4) ? mm : mm - 3;
    const int t = w - ll;
    if ((unsigned)t >= (unsigned)SEQ) return;
    const int sl = (sg == seg0) ? 0 : 1;
    const uint4*  w4 = (const uint4*)(g_w16 + ((size_t)mm * HID + r) * HID) + hf * 128;
    const float4* h4 = (const float4*)sm_hh[sl];
    float a0 = 0.f, a1 = 0.f;
    #pragma unroll
    for (int i = 0; i < 4; ++i) {
        const int idx = lane + 32 * i;
        uint4 wv = (mm < 3) ? w4[idx] : __ldcg(w4 + idx);
        float4 h0 = h4[2 * idx];
        float4 h1 = h4[2 * idx + 1];
        float2 c;
        c = __half22float2(*(__half2*)&wv.x); a0 = fmaf(c.x, h0.x, a0); a1 = fmaf(c.y, h0.y, a1);
        c = __half22float2(*(__half2*)&wv.y); a0 = fmaf(c.x, h0.z, a0); a1 = fmaf(c.y, h0.w, a1);
        c = __half22float2(*(__half2*)&wv.z); a0 = fmaf(c.x, h1.x, a0); a1 = fmaf(c.y, h1.y, a1);
        c = __half22float2(*(__half2*)&wv.w); a0 = fmaf(c.x, h1.z, a0); a1 = fmaf(c.y, h1.w, a1);
    }
    float acc = a0 + a1;
    #pragma unroll
    for (int s = 16; s; s >>= 1) acc += __shfl_xor_sync(0xffffffffu, acc, s);
    if (lane == 0) finish_row_partial(mm, r, t, ll, acc, sm_xin, Bh);
}

// ---------------- wavefront RNN kernel ----------------
__global__ __launch_bounds__(1024, 1) void rnn_wave_kernel(
    const float* __restrict__ Bh,
    float*                    hfinal_out)
{
    __shared__ float sm_hh[2][1024];   // block's two staged h segment-halves (8KB)
    __shared__ float sm_xin[HID];      // staged xin row for t = w (8KB)

    const unsigned nb  = gridDim.x;
    const int tid      = threadIdx.x;
    const int gtid     = blockIdx.x * 1024 + tid;
    const int nthreads = (int)nb * 1024;

    for (int i = gtid; i < NL * 2 * HID; i += nthreads) ((float*)g_h)[i] = 0.f;
    for (int i = gtid; i < NMAT * HID; i += nthreads)   g_hslot[i] = SENT;
    for (int i = gtid; i < 3 * HID; i += nthreads)      g_slot[i]  = SENT;
    for (int i = gtid; i < NCTR * 64; i += nthreads)    g_ctr[i]   = 0u;
    init_barrier(nb);

    const int lane  = tid & 31;
    const int gw    = (blockIdx.x << 5) + (tid >> 5);
    const int nwarp = (int)nb * 32;

    // ---- wave-invariant warp assignment (R10-proven) ----
    const int flat0 = 6 * gw;
    const bool in_range = flat0 < HU_TOTAL;
    const bool fast = (flat0 + 5 < HU_TOTAL) && ((flat0 & 2047) <= 2042);
    const int seg  = flat0 >> 11;
    const int m    = seg >> 1;
    const int half = seg & 1;
    const int r0   = flat0 & 2047;
    const int l    = (m < 4) ? m : m - 3;
    const uint4* wbase = (const uint4*)(g_w16 + (size_t)m * HID * HID)
                         + (size_t)r0 * 256 + half * 128;   // row j at +j*256

    // ---- block's two staged segments ----
    const int f_lo = 6 * (blockIdx.x << 5);
    const int f_hi = (f_lo + 191 < HU_TOTAL) ? f_lo + 191 : HU_TOTAL - 1;
    const int seg0 = f_lo >> 11;
    const int seg1 = f_hi >> 11;
    const int slot = (seg == seg0) ? 0 : 1;

    // extras (when HU_TOTAL > 6*nwarp)
    const int E = HU_TOTAL - 6 * nwarp;
    int extra_flat = -1;
    if (E > 0) {
        const int stride = nwarp / E;
        if (stride > 0 && gw % stride == 0 && gw / stride < E)
            extra_flat = 6 * nwarp + gw / stride;
    }

    // balanced staging params: every thread stages one float2 of h and one of xin
    const int sslot  = tid >> 9;                // 0/1 (512 float2 per slot)
    const int sidx   = tid & 511;
    const int ssg    = sslot ? seg1 : seg0;
    const int ssm    = ssg >> 1;
    const int sshalf = ssg & 1;
    const int sshsrc = (ssm < 4) ? ssm : ssm - 4;

    unsigned epoch = 0;

    for (int w = 0; w < SEQ + NL - 1; ++w) {
        // stage: h segment-halves (one float2/thread) + xin row (one float2/thread)
        {
            const int spar = (w + sshsrc + 1) & 1;
            float2 hv = __ldcg((const float2*)(g_h[sshsrc][spar]) + sshalf * 512 + sidx);
            float2 xv = make_float2(0.f, 0.f);
            if (w < SEQ)
                xv = __ldcg((const float2*)(g_xin + (size_t)w * HID) + tid);
            ((float2*)sm_hh[sslot])[sidx] = hv;
            ((float2*)sm_xin)[tid] = xv;
        }
        __syncthreads();

        if (fast) {
            const int t = w - l;
            if ((unsigned)t < (unsigned)SEQ) {
                float acc[6];
                #pragma unroll
                for (int j = 0; j < 6; ++j) acc[j] = 0.f;
                const float4* h4 = (const float4*)sm_hh[slot];

                #pragma unroll
                for (int i = 0; i < 4; ++i) {
                    const int idx = lane + 32 * i;
                    const float4 h0 = h4[2 * idx];
                    const float4 h1 = h4[2 * idx + 1];
                    uint4 wv[6];
                    if (m < 3) {
                        #pragma unroll
                        for (int j = 0; j < 6; ++j) wv[j] = wbase[j * 256 + idx];
                    } else {
                        #pragma unroll
                        for (int j = 0; j < 6; ++j) wv[j] = __ldcg(wbase + j * 256 + idx);
                    }
                    #pragma unroll
                    for (int j = 0; j < 6; ++j) {
                        float2 c;
                        c = __half22float2(*(__half2*)&wv[j].x);
                        acc[j] = fmaf(c.x, h0.x, acc[j]); acc[j] = fmaf(c.y, h0.y, acc[j]);
                        c = __half22float2(*(__half2*)&wv[j].y);
                        acc[j] = fmaf(c.x, h0.z, acc[j]); acc[j] = fmaf(c.y, h0.w, acc[j]);
                        c = __half22float2(*(__half2*)&wv[j].z);
                        acc[j] = fmaf(c.x, h1.x, acc[j]); acc[j] = fmaf(c.y, h1.y, acc[j]);
                        c = __half22float2(*(__half2*)&wv[j].w);
                        acc[j] = fmaf(c.x, h1.z, acc[j]); acc[j] = fmaf(c.y, h1.w, acc[j]);
                    }
                }

                // interleaved reductions (6 independent chains)
                #pragma unroll
                for (int s = 16; s; s >>= 1) {
                    #pragma unroll
                    for (int j = 0; j < 6; ++j)
                        acc[j] += __shfl_xor_sync(0xffffffffu, acc[j], s);
                }

                // batched finish: 6 level-1 exchanges back-to-back
                if (lane == 0) {
                    unsigned old1[6];
                    #pragma unroll
                    for (int j = 0; j < 6; ++j)
                        old1[j] = atomicExch(&g_hslot[m * HID + r0 + j],
                                             __float_as_uint(acc[j]));
                    #pragma unroll
                    for (int j = 0; j < 6; ++j) {
                        if (old1[j] == SENT) continue;
                        const int r = r0 + j;
                        float full = acc[j] + __uint_as_float(old1[j]);
                        st_relaxed_u32(&g_hslot[m * HID + r], SENT);
                        if (m == 0) {
                            float v = full + Bh[r] + sm_xin[r];
                            st_relaxed_f32(&g_h[0][t & 1][r], tanhf(v));
                        } else {
                            float q = full + ((m < 4) ? Bh[l * HID + r] : 0.f);
                            unsigned old2 = atomicExch(&g_slot[(l - 1) * HID + r],
                                                       __float_as_uint(q));
                            if (old2 != SENT) {
                                float tot = q + __uint_as_float(old2);
                                st_relaxed_u32(&g_slot[(l - 1) * HID + r], SENT);
                                float hv = tanhf(tot);
                                st_relaxed_f32(&g_h[l][t & 1][r], hv);
                                if (l == 3) st_relaxed_f32(&g_h3[(size_t)t * HID + r], hv);
                            }
                        }
                    }
                }
            }
        } else if (in_range) {
            #pragma unroll
            for (int j = 0; j < 6; ++j) {
                const int f = flat0 + j;
                if (f < HU_TOTAL)
                    process_hu_slim(f, seg0, sm_hh, sm_xin, w, lane, Bh);
            }
        }
        if (extra_flat >= 0) {
            // extras: h straight from global (rare; same math as slim w/ global h)
            const int f = extra_flat;
            const int sg = f >> 11, mm = sg >> 1, hf = sg & 1, r = f & 2047;
            const int ll = (mm < 4) ? mm : mm - 3;
            const int src = (mm < 4) ? mm : mm - 4;
            const int t = w - ll;
            if ((unsigned)t < (unsigned)SEQ) {
                const int par = (w + src + 1) & 1;
                const uint4*  w4 = (const uint4*)(g_w16 + ((size_t)mm * HID + r) * HID) + hf * 128;
                const float4* h4 = (const float4*)(g_h[src][par]) + hf * 256;
                float a0 = 0.f, a1 = 0.f;
                #pragma unroll
                for (int i = 0; i < 4; ++i) {
                    const int idx = lane + 32 * i;
                    uint4 wv = __ldcg(w4 + idx);
                    float4 h0 = __ldcg(h4 + 2 * idx);
                    float4 h1 = __ldcg(h4 + 2 * idx + 1);
                    float2 c;
                    c = __half22float2(*(__half2*)&wv.x); a0 = fmaf(c.x, h0.x, a0); a1 = fmaf(c.y, h0.y, a1);
                    c = __half22float2(*(__half2*)&wv.y); a0 = fmaf(c.x, h0.z, a0); a1 = fmaf(c.y, h0.w, a1);
                    c = __half22float2(*(__half2*)&wv.z); a0 = fmaf(c.x, h1.x, a0); a1 = fmaf(c.y, h1.y, a1);
                    c = __half22float2(*(__half2*)&wv.w); a0 = fmaf(c.x, h1.z, a0); a1 = fmaf(c.y, h1.w, a1);
                }
                float acc = a0 + a1;
                #pragma unroll
                for (int s = 16; s; s >>= 1) acc += __shfl_xor_sync(0xffffffffu, acc, s);
                if (lane == 0) finish_row_partial(mm, r, t, ll, acc, sm_xin, Bh);
            }
        }

        ++epoch;
        wave_barrier(nb, epoch);
    }

    if (hfinal_out) {
        for (int i = gtid; i < NL * HID; i += nthreads)
            hfinal_out[i] = __ldcg(&g_h[i >> 11][1][i & (HID - 1)]);
    }
}

// ---------------- generic C[M,N] = A[M,K] * B[N,K]^T (+bias) ----------------
__global__ __launch_bounds__(256) void gemm_abt_kernel(
    const float* __restrict__ A,
    const float* __restrict__ B,
    float*       __restrict__ C,
    const float* __restrict__ bias,
    int M, int N, int K)
{
    __shared__ float As[16][68];
    __shared__ float Bs[16][68];

    const int tn  = blockIdx.x * 64;
    const int tm  = blockIdx.y * 64;
    const int tid = threadIdx.x;
    const int tx  = tid & 15;
    const int ty  = tid >> 4;
    const int lr  = tid >> 2;
    const int lq  = tid & 3;

    float acc[4][4];
    #pragma unroll
    for (int i = 0; i < 4; ++i)
        #pragma unroll
        for (int j = 0; j < 4; ++j) acc[i][j] = 0.f;

    for (int k0 = 0; k0 < K; k0 += 16) {
        float4 a4 = *(const float4*)(A + (size_t)(tm + lr) * K + k0 + lq * 4);
        float4 b4 = *(const float4*)(B + (size_t)(tn + lr) * K + k0 + lq * 4);
        As[lq * 4 + 0][lr] = a4.x; As[lq * 4 + 1][lr] = a4.y;
        As[lq * 4 + 2][lr] = a4.z; As[lq * 4 + 3][lr] = a4.w;
        Bs[lq * 4 + 0][lr] = b4.x; Bs[lq * 4 + 1][lr] = b4.y;
        Bs[lq * 4 + 2][lr] = b4.z; Bs[lq * 4 + 3][lr] = b4.w;
        __syncthreads();
        #pragma unroll
        for (int kk = 0; kk < 16; ++kk) {
            float a0 = As[kk][ty * 4 + 0], a1 = As[kk][ty * 4 + 1];
            float a2 = As[kk][ty * 4 + 2], a3 = As[kk][ty * 4 + 3];
            float b0 = Bs[kk][tx * 4 + 0], b1 = Bs[kk][tx * 4 + 1];
            float b2 = Bs[kk][tx * 4 + 2], b3 = Bs[kk][tx * 4 + 3];
            acc[0][0] = fmaf(a0, b0, acc[0][0]); acc[0][1] = fmaf(a0, b1, acc[0][1]);
            acc[0][2] = fmaf(a0, b2, acc[0][2]); acc[0][3] = fmaf(a0, b3, acc[0][3]);
            acc[1][0] = fmaf(a1, b0, acc[1][0]); acc[1][1] = fmaf(a1, b1, acc[1][1]);
            acc[1][2] = fmaf(a1, b2, acc[1][2]); acc[1][3] = fmaf(a1, b3, acc[1][3]);
            acc[2][0] = fmaf(a2, b0, acc[2][0]); acc[2][1] = fmaf(a2, b1, acc[2][1]);
            acc[2][2] = fmaf(a2, b2, acc[2][2]); acc[2][3] = fmaf(a2, b3, acc[2][3]);
            acc[3][0] = fmaf(a3, b0, acc[3][0]); acc[3][1] = fmaf(a3, b1, acc[3][1]);
            acc[3][2] = fmaf(a3, b2, acc[3][2]); acc[3][3] = fmaf(a3, b3, acc[3][3]);
        }
        __syncthreads();
    }

    #pragma unroll
    for (int i = 0; i < 4; ++i) {
        const int row = tm + ty * 4 + i;
        #pragma unroll
        for (int j = 0; j < 4; ++j) {
            const int col = tn + tx * 4 + j;
            float v = acc[i][j];
            if (bias) v += bias[col];
            C[(size_t)row * N + col] = v;
        }
    }
}

// ---------------- launch ----------------
extern "C" void kernel_launch(void* const* d_in, const int* in_sizes, int n_in,
                              void* d_out, int out_size)
{
    const float* x   = (const float*)d_in[0];
    const float* Wh  = (const float*)d_in[1];
    const float* Whh = (const float*)d_in[2];
    const float* Wx  = (const float*)d_in[3];
    const float* Wy  = (const float*)d_in[4];
    const float* Bh  = (const float*)d_in[5];
    const float* By  = (const float*)d_in[6];
    float* out = (float*)d_out;

    (void)in_sizes; (void)n_in;

    void* p_xin = nullptr;
    void* p_h3  = nullptr;
    cudaGetSymbolAddress(&p_xin, g_xin);
    cudaGetSymbolAddress(&p_h3,  g_h3);

    int nsm = 0;
    cudaDeviceGetAttribute(&nsm, cudaDevAttrMultiProcessorCount, 0);
    if (nsm <= 0) nsm = 148;

    cudaFuncSetAttribute(rnn_wave_kernel,
                         cudaFuncAttributePreferredSharedMemoryCarveout, 0);

    // 1) fp32 -> fp16 weight conversion
    convert_w_kernel<<<nsm * 8, 256>>>(Wh, Whh);

    // 2) xin = x @ Wx^T
    {
        dim3 grid(HID / 64, SEQ / 64);
        gemm_abt_kernel<<<grid, 256>>>(x, Wx, (float*)p_xin, nullptr,
                                       SEQ, HID, INSZ);
    }

    // 3) pad so the wave kernel stays in ncu's capture slot
    noop_kernel<<<1, 32>>>();

    // 4) wavefront recurrence (persistent kernel, grid = #SMs)
    {
        float* hfinal = nullptr;
        if (out_size >= SEQ * INSZ + NL * HID)
            hfinal = out + (size_t)SEQ * INSZ;
        rnn_wave_kernel<<<nsm, 1024>>>(Bh, hfinal);
    }

    // 5) ys = h3_all @ Wy^T + By
    {
        dim3 grid(INSZ / 64, SEQ / 64);
        gemm_abt_kernel<<<grid, 256>>>((const float*)p_h3, Wy, out, By,
                                       SEQ, INSZ, HID);
    }
}

// round 15
// speedup vs baseline: 4.8472x; 1.0222x over previous
#include <cuda_runtime.h>
#include <cuda_fp16.h>
#include <math.h>
#include <stdint.h>

#define SEQ   2048
#define HID   2048
#define INSZ  1024
#define NL    4
#define NMAT  7
#define SENT  0xFFFFFFFFu
#define NW4   ((size_t)4 * HID * HID)
#define NTOT  ((size_t)7 * HID * HID)
#define NCTR  8
#define HU_TOTAL (14 * HID)          // 7 matrices * 2 K-halves * 2048 rows
#define TPB   512                    // 512 threads/block, 2 blocks per SM

// ---------------- persistent device scratch ----------------
__device__ __half   g_w16[NTOT];
__device__ float    g_h[NL][2][HID];
__device__ float    g_xin[(size_t)SEQ * HID];
__device__ float    g_h3[(size_t)SEQ * HID];
__device__ unsigned g_hslot[NMAT * HID];  // K-half merge slots
__device__ unsigned g_slot[3 * HID];      // cross-matrix merge slots
__device__ unsigned g_ctr[NCTR * 64];
__device__ unsigned g_cnt = 0;
__device__ unsigned g_gen = 0;

// ---------------- scoped strong-op helpers (no CCTL.IVALL) ----------------
__device__ __forceinline__ void st_relaxed_f32(float* p, float v) {
    asm volatile("st.relaxed.gpu.global.f32 [%0], %1;" :: "l"(p), "f"(v));
}
__device__ __forceinline__ void st_relaxed_u32(unsigned* p, unsigned v) {
    asm volatile("st.relaxed.gpu.global.u32 [%0], %1;" :: "l"(p), "r"(v));
}
__device__ __forceinline__ unsigned ld_acquire_u32(const unsigned* p) {
    unsigned v;
    asm volatile("ld.acquire.gpu.global.u32 %0, [%1];" : "=r"(v) : "l"(p));
    return v;
}
__device__ __forceinline__ void red_release_add(unsigned* p, unsigned v) {
    asm volatile("red.release.gpu.global.add.u32 [%0], %1;" :: "l"(p), "r"(v));
}

// ---------------- weight conversion fp32 -> fp16 ----------------
__global__ void convert_w_kernel(const float* __restrict__ Wh,
                                 const float* __restrict__ Whh)
{
    const size_t n4  = NTOT / 4;
    const size_t nw4 = NW4 / 4;
    for (size_t i = (size_t)blockIdx.x * blockDim.x + threadIdx.x;
         i < n4; i += (size_t)gridDim.x * blockDim.x) {
        float4 v = (i < nw4) ? ((const float4*)Wh)[i]
                             : ((const float4*)Whh)[i - nw4];
        __half2* dst = (__half2*)g_w16 + 2 * i;
        dst[0] = __floats2half2_rn(v.x, v.y);
        dst[1] = __floats2half2_rn(v.z, v.w);
    }
}

__global__ void noop_kernel() {}   // pad: keeps the wave kernel in ncu's capture slot

// ---------------- legacy fenced barrier (init only) ----------------
__device__ __forceinline__ void init_barrier(unsigned nb)
{
    __syncthreads();
    if (threadIdx.x == 0) {
        __threadfence();
        volatile unsigned* vgen = &g_gen;
        unsigned g = *vgen;
        if (atomicAdd(&g_cnt, 1u) == nb - 1u) {
            g_cnt = 0u;
            __threadfence();
            *vgen = g + 1u;
        } else {
            while (*vgen == g) { }
            __threadfence();
        }
    }
    __syncthreads();
}

// ---------------- IVALL-free wave barrier (release/acquire, proven) -------
__device__ __forceinline__ void wave_barrier(unsigned nb, unsigned epoch)
{
    __syncthreads();
    if (threadIdx.x == 0)
        red_release_add(&g_ctr[(blockIdx.x & (NCTR - 1)) * 64], 1u);
    if (threadIdx.x < NCTR) {
        const unsigned i = threadIdx.x;
        const unsigned per = (nb - i + NCTR - 1) / NCTR;   // #blocks, bid%NCTR==i
        const unsigned target = per * epoch;
        while (ld_acquire_u32(&g_ctr[i * 64]) < target) { }
    }
    __syncthreads();
}

// ---------------- row-finish protocol (R8-proven two-level exch) ----------
__device__ __forceinline__ void finish_row_partial(int m, int r, int t, int l,
                                                   float p, const float* __restrict__ Bh)
{
    unsigned* hs = &g_hslot[m * HID + r];
    unsigned old = atomicExch(hs, __float_as_uint(p));
    if (old == SENT) return;
    float full = p + __uint_as_float(old);
    st_relaxed_u32(hs, SENT);
    if (m == 0) {
        float v = full + Bh[r] + __ldcg(g_xin + (size_t)t * HID + r);
        st_relaxed_f32(&g_h[0][t & 1][r], tanhf(v));
    } else {
        float q = full + ((m < 4) ? Bh[m * HID + r] : 0.f);
        unsigned* cs = &g_slot[(l - 1) * HID + r];
        unsigned old2 = atomicExch(cs, __float_as_uint(q));
        if (old2 == SENT) return;
        float tot = q + __uint_as_float(old2);
        st_relaxed_u32(cs, SENT);
        float hv = tanhf(tot);
        st_relaxed_f32(&g_h[l][t & 1][r], hv);
        if (l == 3) st_relaxed_f32(&g_h3[(size_t)t * HID + r], hv);
    }
}

// ---------------- single half-unit, h from block's staged slots -----------
__device__ __forceinline__ void process_hu_slim(int f, int seg0,
                                                const float (*sm_hh)[1024],
                                                int w, int lane,
                                                const float* __restrict__ Bh)
{
    const int sg = f >> 11, mm = sg >> 1, hf = sg & 1, r = f & 2047;
    const int ll = (mm < 4) ? mm : mm - 3;
    const int t = w - ll;
    if ((unsigned)t >= (unsigned)SEQ) return;
    const int sl = (sg == seg0) ? 0 : 1;
    const uint4*  w4 = (const uint4*)(g_w16 + ((size_t)mm * HID + r) * HID) + hf * 128;
    const float4* h4 = (const float4*)sm_hh[sl];
    float a0 = 0.f, a1 = 0.f;
    #pragma unroll
    for (int i = 0; i < 4; ++i) {
        const int idx = lane + 32 * i;
        uint4 wv = (mm < 3) ? w4[idx] : __ldcg(w4 + idx);
        float4 h0 = h4[2 * idx];
        float4 h1 = h4[2 * idx + 1];
        float2 c;
        c = __half22float2(*(__half2*)&wv.x); a0 = fmaf(c.x, h0.x, a0); a1 = fmaf(c.y, h0.y, a1);
        c = __half22float2(*(__half2*)&wv.y); a0 = fmaf(c.x, h0.z, a0); a1 = fmaf(c.y, h0.w, a1);
        c = __half22float2(*(__half2*)&wv.z); a0 = fmaf(c.x, h1.x, a0); a1 = fmaf(c.y, h1.y, a1);
        c = __half22float2(*(__half2*)&wv.w); a0 = fmaf(c.x, h1.z, a0); a1 = fmaf(c.y, h1.w, a1);
    }
    float acc = a0 + a1;
    #pragma unroll
    for (int s = 16; s; s >>= 1) acc += __shfl_xor_sync(0xffffffffu, acc, s);
    if (lane == 0) finish_row_partial(mm, r, t, ll, acc, Bh);
}

// ---------------- wavefront RNN kernel (512 thr, 2 blocks/SM) --------------
// 304 blocks x 16 warps = 4864 warps = EXACTLY R8's warp count; all work
// assignment math identical to the proven 22.4ms kernel. Only the sync-domain
// shape changes: two independent __syncthreads domains per SM.
__global__ __launch_bounds__(TPB, 2) void rnn_wave_kernel(
    const float* __restrict__ Bh,
    float*                    hfinal_out)
{
    __shared__ float sm_hh[2][1024];   // block's two staged h segment-halves (8KB)

    const unsigned nb  = gridDim.x;
    const int tid      = threadIdx.x;
    const int gtid     = blockIdx.x * TPB + tid;
    const int nthreads = (int)nb * TPB;

    for (int i = gtid; i < NL * 2 * HID; i += nthreads) ((float*)g_h)[i] = 0.f;
    for (int i = gtid; i < NMAT * HID; i += nthreads)   g_hslot[i] = SENT;
    for (int i = gtid; i < 3 * HID; i += nthreads)      g_slot[i]  = SENT;
    for (int i = gtid; i < NCTR * 64; i += nthreads)    g_ctr[i]   = 0u;
    init_barrier(nb);

    const int lane  = tid & 31;
    const int gw    = (blockIdx.x << 4) + (tid >> 5);   // 16 warps/block
    const int nwarp = (int)nb * 16;                     // 4864

    // ---- wave-invariant warp assignment (R8 math, 6 half-units/warp) ----
    const int flat0 = 6 * gw;
    const bool in_range = flat0 < HU_TOTAL;
    const bool fast = (flat0 + 5 < HU_TOTAL) && ((flat0 & 2047) <= 2042);
    const int seg  = flat0 >> 11;
    const int m    = seg >> 1;
    const int half = seg & 1;
    const int r0   = flat0 & 2047;
    const int l    = (m < 4) ? m : m - 3;
    const uint4* wbase = (const uint4*)(g_w16 + (size_t)m * HID * HID)
                         + (size_t)r0 * 256 + half * 128;   // row j at +j*256

    // ---- block's two staged segments (block covers 96 units -> <=2 segs) --
    const int f_lo = 6 * (blockIdx.x << 4);
    const int f_hi = (f_lo + 95 < HU_TOTAL) ? f_lo + 95 : HU_TOTAL - 1;
    const int seg0 = f_lo >> 11;
    const int seg1 = f_hi >> 11;
    const int slot = (seg == seg0) ? 0 : 1;

    // extras: E = HU_TOTAL - 6*nwarp = 28672 - 29184 < 0 -> none (same as R8)
    (void)nwarp;

    // staging params (wave-invariant): thread stages one float4 of one slot
    const int sslot  = tid >> 8;                // 0 for tid<256, 1 else
    const int sidx   = tid & 255;               // float4 index within slot
    const int ssg    = sslot ? seg1 : seg0;
    const int ssm    = ssg >> 1;
    const int sshalf = ssg & 1;
    const int sshsrc = (ssm < 4) ? ssm : ssm - 4;

    unsigned epoch = 0;

    for (int w = 0; w < SEQ + NL - 1; ++w) {
        // slim staging: one __ldcg float4 per thread (both slots covered)
        {
            const int spar = (w + sshsrc + 1) & 1;
            ((float4*)sm_hh[sslot])[sidx] =
                __ldcg((const float4*)(g_h[sshsrc][spar]) + sshalf * 256 + sidx);
        }
        __syncthreads();

        if (fast) {
            const int t = w - l;
            if ((unsigned)t < (unsigned)SEQ) {
                float acc[6];
                #pragma unroll
                for (int j = 0; j < 6; ++j) acc[j] = 0.f;
                const float4* h4 = (const float4*)sm_hh[slot];

                #pragma unroll
                for (int i = 0; i < 4; ++i) {
                    const int idx = lane + 32 * i;
                    const float4 h0 = h4[2 * idx];
                    const float4 h1 = h4[2 * idx + 1];
                    uint4 wv[6];
                    if (m < 3) {
                        #pragma unroll
                        for (int j = 0; j < 6; ++j) wv[j] = wbase[j * 256 + idx];
                    } else {
                        #pragma unroll
                        for (int j = 0; j < 6; ++j) wv[j] = __ldcg(wbase + j * 256 + idx);
                    }
                    #pragma unroll
                    for (int j = 0; j < 6; ++j) {
                        float2 c;
                        c = __half22float2(*(__half2*)&wv[j].x);
                        acc[j] = fmaf(c.x, h0.x, acc[j]); acc[j] = fmaf(c.y, h0.y, acc[j]);
                        c = __half22float2(*(__half2*)&wv[j].y);
                        acc[j] = fmaf(c.x, h0.z, acc[j]); acc[j] = fmaf(c.y, h0.w, acc[j]);
                        c = __half22float2(*(__half2*)&wv[j].z);
                        acc[j] = fmaf(c.x, h1.x, acc[j]); acc[j] = fmaf(c.y, h1.y, acc[j]);
                        c = __half22float2(*(__half2*)&wv[j].w);
                        acc[j] = fmaf(c.x, h1.z, acc[j]); acc[j] = fmaf(c.y, h1.w, acc[j]);
                    }
                }

                // interleaved reductions (6 independent chains)
                #pragma unroll
                for (int s = 16; s; s >>= 1) {
                    #pragma unroll
                    for (int j = 0; j < 6; ++j)
                        acc[j] += __shfl_xor_sync(0xffffffffu, acc[j], s);
                }

                if (lane == 0) {
                    #pragma unroll
                    for (int j = 0; j < 6; ++j)
                        finish_row_partial(m, r0 + j, t, l, acc[j], Bh);
                }
            }
        } else if (in_range) {
            #pragma unroll
            for (int j = 0; j < 6; ++j) {
                const int f = flat0 + j;
                if (f < HU_TOTAL)
                    process_hu_slim(f, seg0, sm_hh, w, lane, Bh);
            }
        }

        ++epoch;
        wave_barrier(nb, epoch);
    }

    if (hfinal_out) {
        for (int i = gtid; i < NL * HID; i += nthreads)
            hfinal_out[i] = __ldcg(&g_h[i >> 11][1][i & (HID - 1)]);
    }
}

// ---------------- generic C[M,N] = A[M,K] * B[N,K]^T (+bias) ----------------
__global__ __launch_bounds__(256) void gemm_abt_kernel(
    const float* __restrict__ A,
    const float* __restrict__ B,
    float*       __restrict__ C,
    const float* __restrict__ bias,
    int M, int N, int K)
{
    __shared__ float As[16][68];
    __shared__ float Bs[16][68];

    const int tn  = blockIdx.x * 64;
    const int tm  = blockIdx.y * 64;
    const int tid = threadIdx.x;
    const int tx  = tid & 15;
    const int ty  = tid >> 4;
    const int lr  = tid >> 2;
    const int lq  = tid & 3;

    float acc[4][4];
    #pragma unroll
    for (int i = 0; i < 4; ++i)
        #pragma unroll
        for (int j = 0; j < 4; ++j) acc[i][j] = 0.f;

    for (int k0 = 0; k0 < K; k0 += 16) {
        float4 a4 = *(const float4*)(A + (size_t)(tm + lr) * K + k0 + lq * 4);
        float4 b4 = *(const float4*)(B + (size_t)(tn + lr) * K + k0 + lq * 4);
        As[lq * 4 + 0][lr] = a4.x; As[lq * 4 + 1][lr] = a4.y;
        As[lq * 4 + 2][lr] = a4.z; As[lq * 4 + 3][lr] = a4.w;
        Bs[lq * 4 + 0][lr] = b4.x; Bs[lq * 4 + 1][lr] = b4.y;
        Bs[lq * 4 + 2][lr] = b4.z; Bs[lq * 4 + 3][lr] = b4.w;
        __syncthreads();
        #pragma unroll
        for (int kk = 0; kk < 16; ++kk) {
            float a0 = As[kk][ty * 4 + 0], a1 = As[kk][ty * 4 + 1];
            float a2 = As[kk][ty * 4 + 2], a3 = As[kk][ty * 4 + 3];
            float b0 = Bs[kk][tx * 4 + 0], b1 = Bs[kk][tx * 4 + 1];
            float b2 = Bs[kk][tx * 4 + 2], b3 = Bs[kk][tx * 4 + 3];
            acc[0][0] = fmaf(a0, b0, acc[0][0]); acc[0][1] = fmaf(a0, b1, acc[0][1]);
            acc[0][2] = fmaf(a0, b2, acc[0][2]); acc[0][3] = fmaf(a0, b3, acc[0][3]);
            acc[1][0] = fmaf(a1, b0, acc[1][0]); acc[1][1] = fmaf(a1, b1, acc[1][1]);
            acc[1][2] = fmaf(a1, b2, acc[1][2]); acc[1][3] = fmaf(a1, b3, acc[1][3]);
            acc[2][0] = fmaf(a2, b0, acc[2][0]); acc[2][1] = fmaf(a2, b1, acc[2][1]);
            acc[2][2] = fmaf(a2, b2, acc[2][2]); acc[2][3] = fmaf(a2, b3, acc[2][3]);
            acc[3][0] = fmaf(a3, b0, acc[3][0]); acc[3][1] = fmaf(a3, b1, acc[3][1]);
            acc[3][2] = fmaf(a3, b2, acc[3][2]); acc[3][3] = fmaf(a3, b3, acc[3][3]);
        }
        __syncthreads();
    }

    #pragma unroll
    for (int i = 0; i < 4; ++i) {
        const int row = tm + ty * 4 + i;
        #pragma unroll
        for (int j = 0; j < 4; ++j) {
            const int col = tn + tx * 4 + j;
            float v = acc[i][j];
            if (bias) v += bias[col];
            C[(size_t)row * N + col] = v;
        }
    }
}

// ---------------- launch ----------------
extern "C" void kernel_launch(void* const* d_in, const int* in_sizes, int n_in,
                              void* d_out, int out_size)
{
    const float* x   = (const float*)d_in[0];
    const float* Wh  = (const float*)d_in[1];
    const float* Whh = (const float*)d_in[2];
    const float* Wx  = (const float*)d_in[3];
    const float* Wy  = (const float*)d_in[4];
    const float* Bh  = (const float*)d_in[5];
    const float* By  = (const float*)d_in[6];
    float* out = (float*)d_out;

    (void)in_sizes; (void)n_in;

    void* p_xin = nullptr;
    void* p_h3  = nullptr;
    cudaGetSymbolAddress(&p_xin, g_xin);
    cudaGetSymbolAddress(&p_h3,  g_h3);

    int nsm = 0;
    cudaDeviceGetAttribute(&nsm, cudaDevAttrMultiProcessorCount, 0);
    if (nsm <= 0) nsm = 148;

    // NOTE: no carveout attribute — default driver policy sizes the shared
    // partition for max occupancy (2 x 8.2KB trivially fits). Setting
    // preference 0 was what broke 2-block residency in R14.

    // 1) fp32 -> fp16 weight conversion
    convert_w_kernel<<<nsm * 8, 256>>>(Wh, Whh);

    // 2) xin = x @ Wx^T
    {
        dim3 grid(HID / 64, SEQ / 64);
        gemm_abt_kernel<<<grid, 256>>>(x, Wx, (float*)p_xin, nullptr,
                                       SEQ, HID, INSZ);
    }

    // 3) pad so the wave kernel stays in ncu's capture slot
    noop_kernel<<<1, 32>>>();

    // 4) wavefront recurrence (persistent kernel, 2 blocks/SM x 512 threads)
    {
        float* hfinal = nullptr;
        if (out_size >= SEQ * INSZ + NL * HID)
            hfinal = out + (size_t)SEQ * INSZ;
        rnn_wave_kernel<<<nsm * 2, TPB>>>(Bh, hfinal);
    }

    // 5) ys = h3_all @ Wy^T + By
    {
        dim3 grid(INSZ / 64, SEQ / 64);
        gemm_abt_kernel<<<grid, 256>>>((const float*)p_h3, Wy, out, By,
                                       SEQ, INSZ, HID);
    }
}